// round 3
// baseline (speedup 1.0000x reference)
#include <cuda_runtime.h>
#include <cstddef>

#define DIMC   384
#define HEADS  12
#define HD     32
#define NTOK   256
#define BATCH  256
#define BHTOT  (BATCH * HEADS)      // 3072
#define MTOT   (BATCH * NTOK)       // 65536
#define KWIN   5
#define EPS    1e-6f

// ---------------- scratch (device globals: allocation-free) ----------------
__device__ float g_q[(size_t)BHTOT * NTOK * HD];
__device__ float g_k[(size_t)BHTOT * NTOK * HD];
__device__ float g_v[(size_t)BHTOT * NTOK * HD];
__device__ float g_y[(size_t)MTOT * DIMC];

// ---------------- GEMM: C[m][n] = sum_k A[m][k] * W[n][k] (+epilogue) ------
// EPI=0: qkv fused epilogue (bias, relu, +pos_enc on k, head-scatter to g_q/g_k/g_v)
// EPI=1: proj epilogue (bias, contiguous store to out); A is taken from g_y.
#define BM 128
#define BN 128
#define BKK 16

template <int EPI>
__global__ void __launch_bounds__(256) gemm_k(
    const float* __restrict__ A, const float* __restrict__ W,
    const float* __restrict__ bias, const float* __restrict__ pos_enc,
    float* __restrict__ Cout)
{
    __shared__ float As[BKK][BM];
    __shared__ float Bs[BKK][BN];

    const int tid = threadIdx.x;
    const int tx = tid & 15;
    const int ty = tid >> 4;
    const int bn = blockIdx.x * BN;
    const int bm = blockIdx.y * BM;
    const int Kd = DIMC;

    const float* Ap = (EPI == 1) ? g_y : A;
    const float* Ab = Ap + (size_t)bm * Kd;
    const float* Wb = W + (size_t)bn * Kd;

    float acc[8][8];
#pragma unroll
    for (int mi = 0; mi < 8; mi++)
#pragma unroll
        for (int ni = 0; ni < 8; ni++) acc[mi][ni] = 0.f;

    const int nkt = Kd / BKK;   // 24
    for (int kt = 0; kt < nkt; kt++) {
#pragma unroll
        for (int l = 0; l < 2; l++) {
            int q4 = tid + l * 256;        // 512 float4 per tile
            int r = q4 >> 2;
            int c4 = (q4 & 3) * 4;
            float4 av = *(const float4*)&Ab[(size_t)r * Kd + kt * BKK + c4];
            As[c4 + 0][r] = av.x; As[c4 + 1][r] = av.y;
            As[c4 + 2][r] = av.z; As[c4 + 3][r] = av.w;
            float4 wv = *(const float4*)&Wb[(size_t)r * Kd + kt * BKK + c4];
            Bs[c4 + 0][r] = wv.x; Bs[c4 + 1][r] = wv.y;
            Bs[c4 + 2][r] = wv.z; Bs[c4 + 3][r] = wv.w;
        }
        __syncthreads();
#pragma unroll
        for (int k = 0; k < BKK; k++) {
            float ar[8], br[8];
            *(float4*)&ar[0] = *(const float4*)&As[k][ty * 8];
            *(float4*)&ar[4] = *(const float4*)&As[k][ty * 8 + 4];
            *(float4*)&br[0] = *(const float4*)&Bs[k][tx * 8];
            *(float4*)&br[4] = *(const float4*)&Bs[k][tx * 8 + 4];
#pragma unroll
            for (int mi = 0; mi < 8; mi++)
#pragma unroll
                for (int ni = 0; ni < 8; ni++)
                    acc[mi][ni] += ar[mi] * br[ni];
        }
        __syncthreads();
    }

    if (EPI == 0) {
        // qkv epilogue: col c in [0,1152): region 0=q, 1=k(+pos,relu), 2=v
#pragma unroll
        for (int mi = 0; mi < 8; mi++) {
            int m = bm + ty * 8 + mi;
            int b = m >> 8;          // batch window
            int i = m & 255;         // token
#pragma unroll
            for (int ni = 0; ni < 8; ni++) {
                int c = bn + tx * 8 + ni;
                float val = acc[mi][ni] + bias[c];
                int region = c / DIMC;
                int ch = c - region * DIMC;
                int h = ch >> 5;
                int d = ch & 31;
                size_t dst = ((size_t)(b * HEADS + h) * NTOK + i) * HD + d;
                if (region == 0) {
                    g_q[dst] = fmaxf(val, 0.f);
                } else if (region == 1) {
                    g_k[dst] = fmaxf(val + pos_enc[(size_t)i * DIMC + ch], 0.f);
                } else {
                    g_v[dst] = val;
                }
            }
        }
    } else {
        // proj epilogue: contiguous vectorized store
#pragma unroll
        for (int mi = 0; mi < 8; mi++) {
            int m = bm + ty * 8 + mi;
            float* dst = Cout + (size_t)m * DIMC + bn + tx * 8;
            const float* bp = bias + bn + tx * 8;
#pragma unroll
            for (int nq = 0; nq < 2; nq++) {
                float4 o;
                o.x = acc[mi][nq * 4 + 0] + bp[nq * 4 + 0];
                o.y = acc[mi][nq * 4 + 1] + bp[nq * 4 + 1];
                o.z = acc[mi][nq * 4 + 2] + bp[nq * 4 + 2];
                o.w = acc[mi][nq * 4 + 3] + bp[nq * 4 + 3];
                *(float4*)&dst[nq * 4] = o;
            }
        }
    }
}

// ---------------- fused linear attention + depthwise conv ------------------
// one block per (b,h). smem: q/k/v tiles [256][33] + kv [32][33] + ksum + conv w/b
#define SM_Q   0
#define SM_K   (256 * 33)
#define SM_V   (2 * 256 * 33)
#define SM_KV  (3 * 256 * 33)          // 25344
#define SM_KS  (SM_KV + 32 * 33)       // 26400
#define SM_W   (SM_KS + 32)            // 26432
#define SM_B   (SM_W + 800)            // 27232
#define SM_FLOATS (SM_B + 32)          // 27264
#define SMEM_BYTES (SM_FLOATS * 4)     // 109056

__global__ void __launch_bounds__(256) attn_kernel(
    const float* __restrict__ dwc_w, const float* __restrict__ dwc_b)
{
    extern __shared__ float sm[];
    float* qs   = sm + SM_Q;
    float* ks   = sm + SM_K;
    float* vs   = sm + SM_V;
    float* kvs  = sm + SM_KV;
    float* ksum = sm + SM_KS;
    float* ws   = sm + SM_W;
    float* bsm  = sm + SM_B;

    const int tid = threadIdx.x;
    const int bh = blockIdx.x;
    const size_t base = (size_t)bh * (NTOK * HD);

    // load q/k/v tiles into padded smem (row pitch 33 -> conflict-free)
    for (int idx = tid; idx < 2048; idx += 256) {
        int row = idx >> 3;
        int col = (idx & 7) * 4;
        float4 t;
        t = *(const float4*)&g_q[base + row * 32 + col];
        qs[row * 33 + col] = t.x; qs[row * 33 + col + 1] = t.y;
        qs[row * 33 + col + 2] = t.z; qs[row * 33 + col + 3] = t.w;
        t = *(const float4*)&g_k[base + row * 32 + col];
        ks[row * 33 + col] = t.x; ks[row * 33 + col + 1] = t.y;
        ks[row * 33 + col + 2] = t.z; ks[row * 33 + col + 3] = t.w;
        t = *(const float4*)&g_v[base + row * 32 + col];
        vs[row * 33 + col] = t.x; vs[row * 33 + col + 1] = t.y;
        vs[row * 33 + col + 2] = t.z; vs[row * 33 + col + 3] = t.w;
    }
    // conv weights (800) + bias (32): grid-stride over 256 threads
    for (int idx = tid; idx < 800; idx += 256) ws[idx] = dwc_w[idx];
    if (tid < 32) bsm[tid] = dwc_b[tid];
    __syncthreads();

    // kv[c][d] = sum_j k[j][c]*v[j][d]; ksum[c] = sum_j k[j][c]
    {
        const int c = tid >> 3;
        const int d0 = tid & 7;
        float a0 = 0.f, a1 = 0.f, a2 = 0.f, a3 = 0.f, s = 0.f;
#pragma unroll 4
        for (int j = 0; j < 256; j++) {
            float kk = ks[j * 33 + c];
            a0 += kk * vs[j * 33 + d0];
            a1 += kk * vs[j * 33 + d0 + 8];
            a2 += kk * vs[j * 33 + d0 + 16];
            a3 += kk * vs[j * 33 + d0 + 24];
            s += kk;
        }
        kvs[c * 33 + d0]      = a0;
        kvs[c * 33 + d0 + 8]  = a1;
        kvs[c * 33 + d0 + 16] = a2;
        kvs[c * 33 + d0 + 24] = a3;
        if (d0 == 0) ksum[c] = s;
    }
    __syncthreads();

    // per-row: out[i][d] = z_i * sum_c q[i][c]*kv[c][d]  + dwconv(v)[i][d] + dwc_b
    const int i = tid;
    float qr[32];
#pragma unroll
    for (int c = 0; c < 32; c++) qr[c] = qs[i * 33 + c];

    float zden = EPS;
#pragma unroll
    for (int c = 0; c < 32; c++) zden += qr[c] * ksum[c];
    const float z = 1.0f / zden;

    float acc[32];
#pragma unroll
    for (int d = 0; d < 32; d++) acc[d] = 0.f;
#pragma unroll
    for (int c = 0; c < 32; c++) {
        float qc = qr[c];
#pragma unroll
        for (int d = 0; d < 32; d++) acc[d] += qc * kvs[c * 33 + d];
    }
#pragma unroll
    for (int d = 0; d < 32; d++) acc[d] *= z;

    // depthwise 5x5 conv: spatial n = a*16 + b_s
    const int a = i >> 4;
    const int b_s = i & 15;
#pragma unroll
    for (int ka = 0; ka < KWIN; ka++) {
        int aa = a + ka - 2;
        if (aa < 0 || aa > 15) continue;
#pragma unroll
        for (int kb = 0; kb < KWIN; kb++) {
            int bb = b_s + kb - 2;
            if (bb < 0 || bb > 15) continue;
            int nn = aa * 16 + bb;
#pragma unroll
            for (int d = 0; d < 32; d++)
                acc[d] += vs[nn * 33 + d] * ws[d * 25 + ka * KWIN + kb];
        }
    }
#pragma unroll
    for (int d = 0; d < 32; d++) acc[d] += bsm[d];

    // merged-head store: y[b][i][h*32+d]
    const int b = bh / HEADS;
    const int h = bh - b * HEADS;
    float* dst = g_y + ((size_t)(b * NTOK + i)) * DIMC + h * HD;
#pragma unroll
    for (int d = 0; d < 32; d += 4) {
        float4 o;
        o.x = acc[d]; o.y = acc[d + 1]; o.z = acc[d + 2]; o.w = acc[d + 3];
        *(float4*)&dst[d] = o;
    }
}

// ---------------- launch ----------------------------------------------------
extern "C" void kernel_launch(void* const* d_in, const int* in_sizes, int n_in,
                              void* d_out, int out_size)
{
    const float* x       = (const float*)d_in[0];
    const float* qkv_w   = (const float*)d_in[1];
    const float* qkv_b   = (const float*)d_in[2];
    const float* pos_enc = (const float*)d_in[3];
    const float* dwc_w   = (const float*)d_in[4];
    const float* dwc_b   = (const float*)d_in[5];
    const float* proj_w  = (const float*)d_in[6];
    const float* proj_b  = (const float*)d_in[7];
    float* out = (float*)d_out;

    cudaFuncSetAttribute(attn_kernel,
                         cudaFuncAttributeMaxDynamicSharedMemorySize, SMEM_BYTES);

    // 1) qkv GEMM + bias + relu + pos_enc + head scatter
    gemm_k<0><<<dim3((3 * DIMC) / BN, MTOT / BM), 256>>>(
        x, qkv_w, qkv_b, pos_enc, nullptr);

    // 2) fused linear attention + depthwise conv -> g_y
    attn_kernel<<<BHTOT, 256, SMEM_BYTES>>>(dwc_w, dwc_b);

    // 3) proj GEMM + bias -> out
    gemm_k<1><<<dim3(DIMC / BN, MTOT / BM), 256>>>(
        nullptr, proj_w, proj_b, nullptr, out);
}

// round 4
// speedup vs baseline: 1.0673x; 1.0673x over previous
#include <cuda_runtime.h>
#include <cstddef>

#define DIMC   384
#define HEADS  12
#define HD     32
#define NTOK   256
#define BATCH  256
#define BHTOT  (BATCH * HEADS)      // 3072
#define MTOT   (BATCH * NTOK)       // 65536
#define KWIN   5
#define EPS    1e-6f

// ---------------- scratch (device globals: allocation-free) ----------------
__device__ float g_q[(size_t)BHTOT * NTOK * HD];
__device__ float g_k[(size_t)BHTOT * NTOK * HD];
__device__ float g_v[(size_t)BHTOT * NTOK * HD];
__device__ float g_y[(size_t)MTOT * DIMC];

// ---------------- GEMM: C[m][n] = sum_k A[m][k] * W[n][k] (+epilogue) ------
// Software-pipelined: double-buffered smem tiles, LDG prefetch into regs
// overlapped with FFMA loop; one __syncthreads per k-tile.
// EPI=0: qkv fused epilogue (bias, relu, +pos_enc on k, head-scatter)
// EPI=1: proj epilogue (bias, contiguous store to out); A taken from g_y.
#define BM 128
#define BN 128
#define BKK 16

template <int EPI>
__global__ void __launch_bounds__(256) gemm_k(
    const float* __restrict__ A, const float* __restrict__ W,
    const float* __restrict__ bias, const float* __restrict__ pos_enc,
    float* __restrict__ Cout)
{
    __shared__ float As[2][BKK][BM];
    __shared__ float Bs[2][BKK][BN];

    const int tid = threadIdx.x;
    const int tx = tid & 15;
    const int ty = tid >> 4;
    const int bn = blockIdx.x * BN;
    const int bm = blockIdx.y * BM;
    const int Kd = DIMC;

    const float* Ap = (EPI == 1) ? g_y : A;
    const float* Ab = Ap + (size_t)bm * Kd;
    const float* Wb = W + (size_t)bn * Kd;

    // per-thread load coords (2 float4 each for A and B per tile)
    int rr[2], cc[2];
#pragma unroll
    for (int l = 0; l < 2; l++) {
        int q4 = tid + l * 256;
        rr[l] = q4 >> 2;
        cc[l] = (q4 & 3) * 4;
    }

    float acc[8][8];
#pragma unroll
    for (int mi = 0; mi < 8; mi++)
#pragma unroll
        for (int ni = 0; ni < 8; ni++) acc[mi][ni] = 0.f;

    float4 pa[2], pw[2];
    // prologue: load tile 0 -> regs -> smem buf 0
#pragma unroll
    for (int l = 0; l < 2; l++) {
        pa[l] = *(const float4*)&Ab[(size_t)rr[l] * Kd + cc[l]];
        pw[l] = *(const float4*)&Wb[(size_t)rr[l] * Kd + cc[l]];
    }
#pragma unroll
    for (int l = 0; l < 2; l++) {
        As[0][cc[l] + 0][rr[l]] = pa[l].x; As[0][cc[l] + 1][rr[l]] = pa[l].y;
        As[0][cc[l] + 2][rr[l]] = pa[l].z; As[0][cc[l] + 3][rr[l]] = pa[l].w;
        Bs[0][cc[l] + 0][rr[l]] = pw[l].x; Bs[0][cc[l] + 1][rr[l]] = pw[l].y;
        Bs[0][cc[l] + 2][rr[l]] = pw[l].z; Bs[0][cc[l] + 3][rr[l]] = pw[l].w;
    }
    __syncthreads();

    const int nkt = Kd / BKK;   // 24
    for (int kt = 0; kt < nkt; kt++) {
        const int cur = kt & 1;
        const bool has_next = (kt + 1 < nkt);

        // issue prefetch LDGs for next tile (latency overlapped with FFMAs)
        if (has_next) {
            int ko = (kt + 1) * BKK;
#pragma unroll
            for (int l = 0; l < 2; l++) {
                pa[l] = *(const float4*)&Ab[(size_t)rr[l] * Kd + ko + cc[l]];
                pw[l] = *(const float4*)&Wb[(size_t)rr[l] * Kd + ko + cc[l]];
            }
        }

#pragma unroll
        for (int k = 0; k < BKK; k++) {
            float ar[8], br[8];
            *(float4*)&ar[0] = *(const float4*)&As[cur][k][ty * 8];
            *(float4*)&ar[4] = *(const float4*)&As[cur][k][ty * 8 + 4];
            *(float4*)&br[0] = *(const float4*)&Bs[cur][k][tx * 8];
            *(float4*)&br[4] = *(const float4*)&Bs[cur][k][tx * 8 + 4];
#pragma unroll
            for (int mi = 0; mi < 8; mi++)
#pragma unroll
                for (int ni = 0; ni < 8; ni++)
                    acc[mi][ni] += ar[mi] * br[ni];
        }

        if (has_next) {
            const int nxt = cur ^ 1;
#pragma unroll
            for (int l = 0; l < 2; l++) {
                As[nxt][cc[l] + 0][rr[l]] = pa[l].x; As[nxt][cc[l] + 1][rr[l]] = pa[l].y;
                As[nxt][cc[l] + 2][rr[l]] = pa[l].z; As[nxt][cc[l] + 3][rr[l]] = pa[l].w;
                Bs[nxt][cc[l] + 0][rr[l]] = pw[l].x; Bs[nxt][cc[l] + 1][rr[l]] = pw[l].y;
                Bs[nxt][cc[l] + 2][rr[l]] = pw[l].z; Bs[nxt][cc[l] + 3][rr[l]] = pw[l].w;
            }
        }
        __syncthreads();
    }

    if (EPI == 0) {
        // qkv epilogue: col c in [0,1152): region 0=q, 1=k(+pos,relu), 2=v
#pragma unroll
        for (int mi = 0; mi < 8; mi++) {
            int m = bm + ty * 8 + mi;
            int b = m >> 8;          // batch window
            int i = m & 255;         // token
#pragma unroll
            for (int ni = 0; ni < 8; ni++) {
                int c = bn + tx * 8 + ni;
                float val = acc[mi][ni] + bias[c];
                int region = c / DIMC;
                int ch = c - region * DIMC;
                int h = ch >> 5;
                int d = ch & 31;
                size_t dst = ((size_t)(b * HEADS + h) * NTOK + i) * HD + d;
                if (region == 0) {
                    g_q[dst] = fmaxf(val, 0.f);
                } else if (region == 1) {
                    g_k[dst] = fmaxf(val + pos_enc[(size_t)i * DIMC + ch], 0.f);
                } else {
                    g_v[dst] = val;
                }
            }
        }
    } else {
        // proj epilogue: contiguous vectorized store
#pragma unroll
        for (int mi = 0; mi < 8; mi++) {
            int m = bm + ty * 8 + mi;
            float* dst = Cout + (size_t)m * DIMC + bn + tx * 8;
            const float* bp = bias + bn + tx * 8;
#pragma unroll
            for (int nq = 0; nq < 2; nq++) {
                float4 o;
                o.x = acc[mi][nq * 4 + 0] + bp[nq * 4 + 0];
                o.y = acc[mi][nq * 4 + 1] + bp[nq * 4 + 1];
                o.z = acc[mi][nq * 4 + 2] + bp[nq * 4 + 2];
                o.w = acc[mi][nq * 4 + 3] + bp[nq * 4 + 3];
                *(float4*)&dst[nq * 4] = o;
            }
        }
    }
}

// ---------------- fused linear attention + depthwise conv ------------------
// one block per (b,h). smem: q/k/v tiles [256][33] + kv [32][33] + ksum + conv w/b
#define SM_Q   0
#define SM_K   (256 * 33)
#define SM_V   (2 * 256 * 33)
#define SM_KV  (3 * 256 * 33)          // 25344
#define SM_KS  (SM_KV + 32 * 33)       // 26400
#define SM_W   (SM_KS + 32)            // 26432
#define SM_B   (SM_W + 800)            // 27232
#define SM_FLOATS (SM_B + 32)          // 27264
#define SMEM_BYTES (SM_FLOATS * 4)     // 109056

__global__ void __launch_bounds__(256) attn_kernel(
    const float* __restrict__ dwc_w, const float* __restrict__ dwc_b)
{
    extern __shared__ float sm[];
    float* qs   = sm + SM_Q;
    float* ks   = sm + SM_K;
    float* vs   = sm + SM_V;
    float* kvs  = sm + SM_KV;
    float* ksum = sm + SM_KS;
    float* ws   = sm + SM_W;
    float* bsm  = sm + SM_B;

    const int tid = threadIdx.x;
    const int bh = blockIdx.x;
    const size_t base = (size_t)bh * (NTOK * HD);

    // load q/k/v tiles into padded smem (row pitch 33 -> conflict-free)
    for (int idx = tid; idx < 2048; idx += 256) {
        int row = idx >> 3;
        int col = (idx & 7) * 4;
        float4 t;
        t = *(const float4*)&g_q[base + row * 32 + col];
        qs[row * 33 + col] = t.x; qs[row * 33 + col + 1] = t.y;
        qs[row * 33 + col + 2] = t.z; qs[row * 33 + col + 3] = t.w;
        t = *(const float4*)&g_k[base + row * 32 + col];
        ks[row * 33 + col] = t.x; ks[row * 33 + col + 1] = t.y;
        ks[row * 33 + col + 2] = t.z; ks[row * 33 + col + 3] = t.w;
        t = *(const float4*)&g_v[base + row * 32 + col];
        vs[row * 33 + col] = t.x; vs[row * 33 + col + 1] = t.y;
        vs[row * 33 + col + 2] = t.z; vs[row * 33 + col + 3] = t.w;
    }
    // conv weights (800) + bias (32): grid-stride over 256 threads
    for (int idx = tid; idx < 800; idx += 256) ws[idx] = dwc_w[idx];
    if (tid < 32) bsm[tid] = dwc_b[tid];
    __syncthreads();

    // kv[c][d] = sum_j k[j][c]*v[j][d]; ksum[c] = sum_j k[j][c]
    {
        const int c = tid >> 3;
        const int d0 = tid & 7;
        float a0 = 0.f, a1 = 0.f, a2 = 0.f, a3 = 0.f, s = 0.f;
#pragma unroll 4
        for (int j = 0; j < 256; j++) {
            float kk = ks[j * 33 + c];
            a0 += kk * vs[j * 33 + d0];
            a1 += kk * vs[j * 33 + d0 + 8];
            a2 += kk * vs[j * 33 + d0 + 16];
            a3 += kk * vs[j * 33 + d0 + 24];
            s += kk;
        }
        kvs[c * 33 + d0]      = a0;
        kvs[c * 33 + d0 + 8]  = a1;
        kvs[c * 33 + d0 + 16] = a2;
        kvs[c * 33 + d0 + 24] = a3;
        if (d0 == 0) ksum[c] = s;
    }
    __syncthreads();

    // per-row: out[i][d] = z_i * sum_c q[i][c]*kv[c][d]  + dwconv(v)[i][d] + dwc_b
    const int i = tid;
    float qr[32];
#pragma unroll
    for (int c = 0; c < 32; c++) qr[c] = qs[i * 33 + c];

    float zden = EPS;
#pragma unroll
    for (int c = 0; c < 32; c++) zden += qr[c] * ksum[c];
    const float z = 1.0f / zden;

    float acc[32];
#pragma unroll
    for (int d = 0; d < 32; d++) acc[d] = 0.f;
#pragma unroll
    for (int c = 0; c < 32; c++) {
        float qc = qr[c];
#pragma unroll
        for (int d = 0; d < 32; d++) acc[d] += qc * kvs[c * 33 + d];
    }
#pragma unroll
    for (int d = 0; d < 32; d++) acc[d] *= z;

    // depthwise 5x5 conv: spatial n = a*16 + b_s
    const int a = i >> 4;
    const int b_s = i & 15;
#pragma unroll
    for (int ka = 0; ka < KWIN; ka++) {
        int aa = a + ka - 2;
        if (aa < 0 || aa > 15) continue;
#pragma unroll
        for (int kb = 0; kb < KWIN; kb++) {
            int bb = b_s + kb - 2;
            if (bb < 0 || bb > 15) continue;
            int nn = aa * 16 + bb;
#pragma unroll
            for (int d = 0; d < 32; d++)
                acc[d] += vs[nn * 33 + d] * ws[d * 25 + ka * KWIN + kb];
        }
    }
#pragma unroll
    for (int d = 0; d < 32; d++) acc[d] += bsm[d];

    // merged-head store: y[b][i][h*32+d]
    const int b = bh / HEADS;
    const int h = bh - b * HEADS;
    float* dst = g_y + ((size_t)(b * NTOK + i)) * DIMC + h * HD;
#pragma unroll
    for (int d = 0; d < 32; d += 4) {
        float4 o;
        o.x = acc[d]; o.y = acc[d + 1]; o.z = acc[d + 2]; o.w = acc[d + 3];
        *(float4*)&dst[d] = o;
    }
}

// ---------------- launch ----------------------------------------------------
extern "C" void kernel_launch(void* const* d_in, const int* in_sizes, int n_in,
                              void* d_out, int out_size)
{
    const float* x       = (const float*)d_in[0];
    const float* qkv_w   = (const float*)d_in[1];
    const float* qkv_b   = (const float*)d_in[2];
    const float* pos_enc = (const float*)d_in[3];
    const float* dwc_w   = (const float*)d_in[4];
    const float* dwc_b   = (const float*)d_in[5];
    const float* proj_w  = (const float*)d_in[6];
    const float* proj_b  = (const float*)d_in[7];
    float* out = (float*)d_out;

    cudaFuncSetAttribute(attn_kernel,
                         cudaFuncAttributeMaxDynamicSharedMemorySize, SMEM_BYTES);

    // 1) qkv GEMM + bias + relu + pos_enc + head scatter
    gemm_k<0><<<dim3((3 * DIMC) / BN, MTOT / BM), 256>>>(
        x, qkv_w, qkv_b, pos_enc, nullptr);

    // 2) fused linear attention + depthwise conv -> g_y
    attn_kernel<<<BHTOT, 256, SMEM_BYTES>>>(dwc_w, dwc_b);

    // 3) proj GEMM + bias -> out
    gemm_k<1><<<dim3(DIMC / BN, MTOT / BM), 256>>>(
        nullptr, proj_w, proj_b, nullptr, out);
}